// round 10
// baseline (speedup 1.0000x reference)
#include <cuda_runtime.h>
#include <cuda_bf16.h>

// Problem constants (capacities for static scratch; runtime dims from in_sizes)
#define NMAX 100000
#define EMAX 1600000
#define HID  64
#define NBMAX 128   // max scan blocks: ceil(NMAX/1024) = 98

// ---------------- static device scratch (no allocation allowed) ----------------
__device__ int   g_cnt[NMAX];          // in-degree counts (no self loop)
__device__ float g_dinv[NMAX];         // deg^{-1/2} incl. self loop
__device__ int   g_rowptr[NMAX + 1];   // CSR offsets by target (col)
__device__ int   g_cursor[NMAX];       // fill cursors
__device__ int   g_bsum[NBMAX];        // per-block scan totals
__device__ int   g_boff[NBMAX];        // exclusive block offsets
__device__ __align__(16) int2 g_edge[EMAX];   // CSR slot: {src, norm-bits}
__device__ __align__(16) float g_bufA[(size_t)NMAX * HID];  // x@W1, later h1@W2
__device__ __align__(16) float g_bufB[(size_t)NMAX * HID];  // relu(agg1)+b1

// ---------------- graph prep kernels ----------------
__global__ void k_zero_cnt(int n) {
    int i = blockIdx.x * blockDim.x + threadIdx.x;
    if (i < n) g_cnt[i] = 0;
}

// edge_index is int32 (JAX default x64-disabled downgrades int64 -> int32)
__global__ void k_count(const int* __restrict__ ei, int E, int n) {
    int e = blockIdx.x * blockDim.x + threadIdx.x;
    if (e < E) {
        int c = ei[E + e];  // col = target
        if ((unsigned)c < (unsigned)n) atomicAdd(&g_cnt[c], 1);
    }
}

__global__ void k_dinv(int n) {
    int i = blockIdx.x * blockDim.x + threadIdx.x;
    if (i < n) g_dinv[i] = rsqrtf((float)(g_cnt[i] + 1));  // +1 self loop
}

// ---- 3-phase grid-wide exclusive scan over g_cnt -> g_rowptr / g_cursor ----
__global__ void k_scan_local(int n) {
    __shared__ int sh[1024];
    int t = threadIdx.x;
    int i = blockIdx.x * 1024 + t;
    int v = (i < n) ? g_cnt[i] : 0;
    sh[t] = v;
    __syncthreads();
#pragma unroll
    for (int d = 1; d < 1024; d <<= 1) {
        int u = (t >= d) ? sh[t - d] : 0;
        __syncthreads();
        sh[t] += u;
        __syncthreads();
    }
    if (i < n) g_rowptr[i] = sh[t] - v;           // exclusive within block
    if (t == 1023) g_bsum[blockIdx.x] = sh[1023]; // block total
}

__global__ void k_scan_bsum(int nb, int n) {
    __shared__ int sh[NBMAX];
    int t = threadIdx.x;  // blockDim.x == NBMAX
    int v = (t < nb) ? g_bsum[t] : 0;
    sh[t] = v;
    __syncthreads();
#pragma unroll
    for (int d = 1; d < NBMAX; d <<= 1) {
        int u = (t >= d) ? sh[t - d] : 0;
        __syncthreads();
        sh[t] += u;
        __syncthreads();
    }
    if (t < nb) g_boff[t] = sh[t] - v;            // exclusive block offset
    if (t == NBMAX - 1) g_rowptr[n] = sh[NBMAX - 1];  // grand total
}

__global__ void k_scan_fixup(int n) {
    int i = blockIdx.x * blockDim.x + threadIdx.x;
    if (i < n) {
        int val = g_rowptr[i] + g_boff[i >> 10];
        g_rowptr[i] = val;
        g_cursor[i] = val;
    }
}

__global__ void k_fill(const int* __restrict__ ei, int E, int n) {
    int e = blockIdx.x * blockDim.x + threadIdx.x;
    if (e < E) {
        int r = ei[e];          // source
        int c = ei[E + e];      // target
        if ((unsigned)r < (unsigned)n && (unsigned)c < (unsigned)n) {
            int p = atomicAdd(&g_cursor[c], 1);
            float nm = g_dinv[r] * g_dinv[c];
            g_edge[p] = make_int2(r, __float_as_int(nm));  // one 8B scattered store
        }
    }
}

// ---------------- dense transform: C[n,64] = A[n,K] @ W[K,64] ----------------
// 64x64 tile per block, 256 threads, 4x4 micro-tile, K-chunks of 32.
template <int K, bool SRC_EXT>
__global__ void k_gemm64(const float* __restrict__ Aext, const float* __restrict__ W,
                         int n) {
    const float* __restrict__ A = SRC_EXT ? Aext : (const float*)g_bufB;
    float* __restrict__ C = g_bufA;

    __shared__ float xs[64][33];
    __shared__ __align__(16) float ws[32][68];
    int tid = threadIdx.x;
    int tx = tid & 15;
    int ty = tid >> 4;
    int bm = blockIdx.x * 64;

    float acc[4][4] = {};

    for (int k0 = 0; k0 < K; k0 += 32) {
        for (int l = tid; l < 64 * 32; l += 256) {
            int m = l >> 5, kk = l & 31;
            int r = bm + m;
            xs[m][kk] = (r < n) ? A[(size_t)r * K + k0 + kk] : 0.0f;
        }
        for (int l = tid; l < 32 * 64; l += 256) {
            int kk = l >> 6, c = l & 63;
            ws[kk][c] = W[(size_t)(k0 + kk) * 64 + c];
        }
        __syncthreads();
#pragma unroll
        for (int kk = 0; kk < 32; kk++) {
            float a0 = xs[ty * 4 + 0][kk];
            float a1 = xs[ty * 4 + 1][kk];
            float a2 = xs[ty * 4 + 2][kk];
            float a3 = xs[ty * 4 + 3][kk];
            float4 b = *(const float4*)&ws[kk][tx * 4];
            acc[0][0] += a0 * b.x; acc[0][1] += a0 * b.y; acc[0][2] += a0 * b.z; acc[0][3] += a0 * b.w;
            acc[1][0] += a1 * b.x; acc[1][1] += a1 * b.y; acc[1][2] += a1 * b.z; acc[1][3] += a1 * b.w;
            acc[2][0] += a2 * b.x; acc[2][1] += a2 * b.y; acc[2][2] += a2 * b.z; acc[2][3] += a2 * b.w;
            acc[3][0] += a3 * b.x; acc[3][1] += a3 * b.y; acc[3][2] += a3 * b.z; acc[3][3] += a3 * b.w;
        }
        __syncthreads();
    }

#pragma unroll
    for (int i = 0; i < 4; i++) {
        int r = bm + ty * 4 + i;
        if (r < n) {
            float4 v = make_float4(acc[i][0], acc[i][1], acc[i][2], acc[i][3]);
            *(float4*)&C[(size_t)r * 64 + tx * 4] = v;
        }
    }
}

// ---------------- aggregation (CSR gather by target node) ----------------
// 16 threads per node (float4 per thread), 16 node-slots per block,
// grid-stride over nodes so per-node degree variance averages out.
template <bool RELU, bool OUT_EXT>
__global__ void k_agg(const float* __restrict__ b, float* __restrict__ outExt, int n) {
    const float4* __restrict__ h4 = (const float4*)g_bufA;
    float* __restrict__ outp = OUT_EXT ? outExt : g_bufB;

    int fx = threadIdx.x;                               // 0..15 (feature group)
    float4 bb = ((const float4*)b)[fx];
    int stride = gridDim.x * 16;

    for (int node = blockIdx.x * 16 + threadIdx.y; node < n; node += stride) {
        float di = g_dinv[node];
        float w = di * di;
        float4 hv = h4[(size_t)node * 16 + fx];
        float4 acc = make_float4(w * hv.x, w * hv.y, w * hv.z, w * hv.w);

        int e = g_rowptr[node];
        int e_end = g_rowptr[node + 1];

        for (; e + 4 <= e_end; e += 4) {
            int2 e0 = g_edge[e + 0], e1 = g_edge[e + 1], e2 = g_edge[e + 2], e3 = g_edge[e + 3];
            float w0 = __int_as_float(e0.y), w1 = __int_as_float(e1.y);
            float w2 = __int_as_float(e2.y), w3 = __int_as_float(e3.y);
            float4 v0 = h4[(size_t)e0.x * 16 + fx];
            float4 v1 = h4[(size_t)e1.x * 16 + fx];
            float4 v2 = h4[(size_t)e2.x * 16 + fx];
            float4 v3 = h4[(size_t)e3.x * 16 + fx];
            acc.x += w0 * v0.x + w1 * v1.x + w2 * v2.x + w3 * v3.x;
            acc.y += w0 * v0.y + w1 * v1.y + w2 * v2.y + w3 * v3.y;
            acc.z += w0 * v0.z + w1 * v1.z + w2 * v2.z + w3 * v3.z;
            acc.w += w0 * v0.w + w1 * v1.w + w2 * v2.w + w3 * v3.w;
        }
        for (; e < e_end; e++) {
            int2 ed = g_edge[e];
            float nm = __int_as_float(ed.y);
            float4 v = h4[(size_t)ed.x * 16 + fx];
            acc.x += nm * v.x; acc.y += nm * v.y; acc.z += nm * v.z; acc.w += nm * v.w;
        }

        acc.x += bb.x; acc.y += bb.y; acc.z += bb.z; acc.w += bb.w;
        if (RELU) {
            acc.x = fmaxf(acc.x, 0.0f); acc.y = fmaxf(acc.y, 0.0f);
            acc.z = fmaxf(acc.z, 0.0f); acc.w = fmaxf(acc.w, 0.0f);
        }
        *(float4*)&outp[(size_t)node * 64 + fx * 4] = acc;
    }
}

// ---------------- launch ----------------
// One-time host-side resources (not device memory; legal).
static cudaStream_t get_s2() {
    static cudaStream_t s = [] {
        cudaStream_t t;
        cudaStreamCreateWithFlags(&t, cudaStreamNonBlocking);
        return t;
    }();
    return s;
}
static cudaEvent_t get_ev(int which) {
    static cudaEvent_t e0 = [] {
        cudaEvent_t e;
        cudaEventCreateWithFlags(&e, cudaEventDisableTiming);
        return e;
    }();
    static cudaEvent_t e1 = [] {
        cudaEvent_t e;
        cudaEventCreateWithFlags(&e, cudaEventDisableTiming);
        return e;
    }();
    return which ? e1 : e0;
}

extern "C" void kernel_launch(void* const* d_in, const int* in_sizes, int n_in,
                              void* d_out, int out_size) {
    const float* x  = (const float*)d_in[0];
    const int*   ei = (const int*)d_in[1];     // int32 edge_index [2, E]
    const float* W1 = (const float*)d_in[2];
    const float* b1 = (const float*)d_in[3];
    const float* W2 = (const float*)d_in[4];
    const float* b2 = (const float*)d_in[5];
    float*       out = (float*)d_out;

    const int hid   = in_sizes[3];                // 64
    const int in_ch = in_sizes[2] / hid;          // 128
    const int n     = in_sizes[0] / in_ch;        // 100000
    const int E     = in_sizes[1] / 2;            // 1600000

    const int T = 256;
    const int gN = (n + T - 1) / T;
    const int gE = (E + T - 1) / T;
    const int nb = (n + 1023) / 1024;             // 98 scan blocks
    const int gG = (n + 63) / 64;
    dim3 aggBlock(16, 16);                        // 16 thr/node, 16 node-slots
    const int gA = 1184;                          // 8 blocks/SM, grid-stride

    cudaStream_t s2 = get_s2();
    cudaEvent_t evFork = get_ev(0);
    cudaEvent_t evJoin = get_ev(1);

    // Fork: GEMM1 (x@W1 -> bufA) is independent of the graph-prep chain.
    cudaEventRecord(evFork, 0);
    cudaStreamWaitEvent(s2, evFork, 0);
    k_gemm64<128, true><<<gG, 256, 0, s2>>>(x, W1, n);
    cudaEventRecord(evJoin, s2);

    // Graph prep on the origin stream (concurrent with GEMM1).
    k_zero_cnt<<<gN, T>>>(n);
    k_count<<<gE, T>>>(ei, E, n);
    k_dinv<<<gN, T>>>(n);
    k_scan_local<<<nb, 1024>>>(n);
    k_scan_bsum<<<1, NBMAX>>>(nb, n);
    k_scan_fixup<<<gN, T>>>(n);
    k_fill<<<gE, T>>>(ei, E, n);

    // Join: agg1 needs both CSR and bufA.
    cudaStreamWaitEvent(0, evJoin, 0);

    // layer 1 aggregate: bufB = relu(agg(bufA) + b1)
    k_agg<true, false><<<gA, aggBlock>>>(b1, nullptr, n);

    // layer 2: bufA = bufB@W2 ; out = agg(bufA) + b2
    k_gemm64<64, false><<<gG, 256>>>(nullptr, W2, n);
    k_agg<false, true><<<gA, aggBlock>>>(b2, out, n);
}

// round 11
// speedup vs baseline: 1.1642x; 1.1642x over previous
#include <cuda_runtime.h>
#include <cuda_bf16.h>

// Problem constants (capacities for static scratch; runtime dims from in_sizes)
#define NMAX 100000
#define EMAX 1600000
#define HID  64
#define NBMAX 128   // max scan blocks: ceil(NMAX/1024) = 98

// ---------------- static device scratch (no allocation allowed) ----------------
__device__ int   g_cnt[NMAX];          // in-degree counts (no self loop)
__device__ float g_dinv[NMAX];         // deg^{-1/2} incl. self loop
__device__ int   g_rowptr[NMAX + 1];   // CSR offsets by target (col)
__device__ int   g_cursor[NMAX];       // fill cursors
__device__ int   g_bsum[NBMAX];        // per-block scan totals
__device__ int   g_boff[NBMAX];        // exclusive block offsets
__device__ __align__(16) int2 g_edge[EMAX];   // CSR slot: {src, norm-bits}
__device__ __align__(16) float g_bufA[(size_t)NMAX * HID];  // x@W1, later h1@W2
__device__ __align__(16) float g_bufB[(size_t)NMAX * HID];  // relu(agg1)+b1

// ---------------- graph prep kernels ----------------
__global__ void k_zero_cnt(int n) {
    int i = blockIdx.x * blockDim.x + threadIdx.x;
    if (i < n) g_cnt[i] = 0;
}

// edge_index is int32 (JAX default x64-disabled downgrades int64 -> int32)
__global__ void k_count(const int* __restrict__ ei, int E, int n) {
    int e = blockIdx.x * blockDim.x + threadIdx.x;
    if (e < E) {
        int c = ei[E + e];  // col = target
        if ((unsigned)c < (unsigned)n) atomicAdd(&g_cnt[c], 1);
    }
}

__global__ void k_dinv(int n) {
    int i = blockIdx.x * blockDim.x + threadIdx.x;
    if (i < n) g_dinv[i] = rsqrtf((float)(g_cnt[i] + 1));  // +1 self loop
}

// ---- 3-phase grid-wide exclusive scan over g_cnt -> g_rowptr / g_cursor ----
__global__ void k_scan_local(int n) {
    __shared__ int sh[1024];
    int t = threadIdx.x;
    int i = blockIdx.x * 1024 + t;
    int v = (i < n) ? g_cnt[i] : 0;
    sh[t] = v;
    __syncthreads();
#pragma unroll
    for (int d = 1; d < 1024; d <<= 1) {
        int u = (t >= d) ? sh[t - d] : 0;
        __syncthreads();
        sh[t] += u;
        __syncthreads();
    }
    if (i < n) g_rowptr[i] = sh[t] - v;           // exclusive within block
    if (t == 1023) g_bsum[blockIdx.x] = sh[1023]; // block total
}

__global__ void k_scan_bsum(int nb, int n) {
    __shared__ int sh[NBMAX];
    int t = threadIdx.x;  // blockDim.x == NBMAX
    int v = (t < nb) ? g_bsum[t] : 0;
    sh[t] = v;
    __syncthreads();
#pragma unroll
    for (int d = 1; d < NBMAX; d <<= 1) {
        int u = (t >= d) ? sh[t - d] : 0;
        __syncthreads();
        sh[t] += u;
        __syncthreads();
    }
    if (t < nb) g_boff[t] = sh[t] - v;            // exclusive block offset
    if (t == NBMAX - 1) g_rowptr[n] = sh[NBMAX - 1];  // grand total
}

__global__ void k_scan_fixup(int n) {
    int i = blockIdx.x * blockDim.x + threadIdx.x;
    if (i < n) {
        int val = g_rowptr[i] + g_boff[i >> 10];
        g_rowptr[i] = val;
        g_cursor[i] = val;
    }
}

__global__ void k_fill(const int* __restrict__ ei, int E, int n) {
    int e = blockIdx.x * blockDim.x + threadIdx.x;
    if (e < E) {
        int r = ei[e];          // source
        int c = ei[E + e];      // target
        if ((unsigned)r < (unsigned)n && (unsigned)c < (unsigned)n) {
            int p = atomicAdd(&g_cursor[c], 1);
            float nm = g_dinv[r] * g_dinv[c];
            g_edge[p] = make_int2(r, __float_as_int(nm));  // one 8B scattered store
        }
    }
}

// ---------------- dense transform: C[n,64] = A[n,K] @ W[K,64] ----------------
// 64x64 tile per block, 256 threads, 4x4 micro-tile, K-chunks of 32.
template <int K, bool SRC_EXT>
__global__ void k_gemm64(const float* __restrict__ Aext, const float* __restrict__ W,
                         int n) {
    const float* __restrict__ A = SRC_EXT ? Aext : (const float*)g_bufB;
    float* __restrict__ C = g_bufA;

    __shared__ float xs[64][33];
    __shared__ __align__(16) float ws[32][68];
    int tid = threadIdx.x;
    int tx = tid & 15;
    int ty = tid >> 4;
    int bm = blockIdx.x * 64;

    float acc[4][4] = {};

    for (int k0 = 0; k0 < K; k0 += 32) {
        for (int l = tid; l < 64 * 32; l += 256) {
            int m = l >> 5, kk = l & 31;
            int r = bm + m;
            xs[m][kk] = (r < n) ? A[(size_t)r * K + k0 + kk] : 0.0f;
        }
        for (int l = tid; l < 32 * 64; l += 256) {
            int kk = l >> 6, c = l & 63;
            ws[kk][c] = W[(size_t)(k0 + kk) * 64 + c];
        }
        __syncthreads();
#pragma unroll
        for (int kk = 0; kk < 32; kk++) {
            float a0 = xs[ty * 4 + 0][kk];
            float a1 = xs[ty * 4 + 1][kk];
            float a2 = xs[ty * 4 + 2][kk];
            float a3 = xs[ty * 4 + 3][kk];
            float4 b = *(const float4*)&ws[kk][tx * 4];
            acc[0][0] += a0 * b.x; acc[0][1] += a0 * b.y; acc[0][2] += a0 * b.z; acc[0][3] += a0 * b.w;
            acc[1][0] += a1 * b.x; acc[1][1] += a1 * b.y; acc[1][2] += a1 * b.z; acc[1][3] += a1 * b.w;
            acc[2][0] += a2 * b.x; acc[2][1] += a2 * b.y; acc[2][2] += a2 * b.z; acc[2][3] += a2 * b.w;
            acc[3][0] += a3 * b.x; acc[3][1] += a3 * b.y; acc[3][2] += a3 * b.z; acc[3][3] += a3 * b.w;
        }
        __syncthreads();
    }

#pragma unroll
    for (int i = 0; i < 4; i++) {
        int r = bm + ty * 4 + i;
        if (r < n) {
            float4 v = make_float4(acc[i][0], acc[i][1], acc[i][2], acc[i][3]);
            *(float4*)&C[(size_t)r * 64 + tx * 4] = v;
        }
    }
}

// ---------------- aggregation (CSR gather by target node) ----------------
// 16 threads per node (float4 per thread), 16 nodes per block, fixed mapping.
// Edge loop unrolled x4 with packed int2 edge records -> MLP ~4.
template <bool RELU, bool OUT_EXT>
__global__ void k_agg(const float* __restrict__ b, float* __restrict__ outExt, int n) {
    const float4* __restrict__ h4 = (const float4*)g_bufA;
    float* __restrict__ outp = OUT_EXT ? outExt : g_bufB;

    int fx = threadIdx.x;                               // 0..15 (feature group)
    int node = blockIdx.x * 16 + threadIdx.y;
    if (node >= n) return;

    float di = g_dinv[node];
    float w = di * di;
    float4 hv = h4[(size_t)node * 16 + fx];
    float4 acc = make_float4(w * hv.x, w * hv.y, w * hv.z, w * hv.w);

    int e = g_rowptr[node];
    int e_end = g_rowptr[node + 1];

    for (; e + 4 <= e_end; e += 4) {
        int2 e0 = g_edge[e + 0], e1 = g_edge[e + 1], e2 = g_edge[e + 2], e3 = g_edge[e + 3];
        float w0 = __int_as_float(e0.y), w1 = __int_as_float(e1.y);
        float w2 = __int_as_float(e2.y), w3 = __int_as_float(e3.y);
        float4 v0 = h4[(size_t)e0.x * 16 + fx];
        float4 v1 = h4[(size_t)e1.x * 16 + fx];
        float4 v2 = h4[(size_t)e2.x * 16 + fx];
        float4 v3 = h4[(size_t)e3.x * 16 + fx];
        acc.x += w0 * v0.x + w1 * v1.x + w2 * v2.x + w3 * v3.x;
        acc.y += w0 * v0.y + w1 * v1.y + w2 * v2.y + w3 * v3.y;
        acc.z += w0 * v0.z + w1 * v1.z + w2 * v2.z + w3 * v3.z;
        acc.w += w0 * v0.w + w1 * v1.w + w2 * v2.w + w3 * v3.w;
    }
    for (; e < e_end; e++) {
        int2 ed = g_edge[e];
        float nm = __int_as_float(ed.y);
        float4 v = h4[(size_t)ed.x * 16 + fx];
        acc.x += nm * v.x; acc.y += nm * v.y; acc.z += nm * v.z; acc.w += nm * v.w;
    }

    float4 bb = ((const float4*)b)[fx];
    acc.x += bb.x; acc.y += bb.y; acc.z += bb.z; acc.w += bb.w;
    if (RELU) {
        acc.x = fmaxf(acc.x, 0.0f); acc.y = fmaxf(acc.y, 0.0f);
        acc.z = fmaxf(acc.z, 0.0f); acc.w = fmaxf(acc.w, 0.0f);
    }
    *(float4*)&outp[(size_t)node * 64 + fx * 4] = acc;
}

// ---------------- launch ----------------
// One-time host-side resources (not device memory; legal).
static cudaStream_t get_s2() {
    static cudaStream_t s = [] {
        cudaStream_t t;
        cudaStreamCreateWithFlags(&t, cudaStreamNonBlocking);
        return t;
    }();
    return s;
}
static cudaEvent_t get_ev(int which) {
    static cudaEvent_t e0 = [] {
        cudaEvent_t e;
        cudaEventCreateWithFlags(&e, cudaEventDisableTiming);
        return e;
    }();
    static cudaEvent_t e1 = [] {
        cudaEvent_t e;
        cudaEventCreateWithFlags(&e, cudaEventDisableTiming);
        return e;
    }();
    return which ? e1 : e0;
}

extern "C" void kernel_launch(void* const* d_in, const int* in_sizes, int n_in,
                              void* d_out, int out_size) {
    const float* x  = (const float*)d_in[0];
    const int*   ei = (const int*)d_in[1];     // int32 edge_index [2, E]
    const float* W1 = (const float*)d_in[2];
    const float* b1 = (const float*)d_in[3];
    const float* W2 = (const float*)d_in[4];
    const float* b2 = (const float*)d_in[5];
    float*       out = (float*)d_out;

    const int hid   = in_sizes[3];                // 64
    const int in_ch = in_sizes[2] / hid;          // 128
    const int n     = in_sizes[0] / in_ch;        // 100000
    const int E     = in_sizes[1] / 2;            // 1600000

    const int T = 256;
    const int gN = (n + T - 1) / T;
    const int gE = (E + T - 1) / T;
    const int nb = (n + 1023) / 1024;             // 98 scan blocks
    const int gG = (n + 63) / 64;
    dim3 aggBlock(16, 16);                        // 16 thr/node, 16 nodes/block
    const int gA = (n + 15) / 16;                 // fixed one-node-per-slot

    cudaStream_t s2 = get_s2();
    cudaEvent_t evFork = get_ev(0);
    cudaEvent_t evJoin = get_ev(1);

    // Fork: GEMM1 (x@W1 -> bufA) is independent of the graph-prep chain.
    cudaEventRecord(evFork, 0);
    cudaStreamWaitEvent(s2, evFork, 0);
    k_gemm64<128, true><<<gG, 256, 0, s2>>>(x, W1, n);
    cudaEventRecord(evJoin, s2);

    // Graph prep on the origin stream (concurrent with GEMM1).
    k_zero_cnt<<<gN, T>>>(n);
    k_count<<<gE, T>>>(ei, E, n);
    k_dinv<<<gN, T>>>(n);
    k_scan_local<<<nb, 1024>>>(n);
    k_scan_bsum<<<1, NBMAX>>>(nb, n);
    k_scan_fixup<<<gN, T>>>(n);
    k_fill<<<gE, T>>>(ei, E, n);

    // Join: agg1 needs both CSR and bufA.
    cudaStreamWaitEvent(0, evJoin, 0);

    // layer 1 aggregate: bufB = relu(agg(bufA) + b1)
    k_agg<true, false><<<gA, aggBlock>>>(b1, nullptr, n);

    // layer 2: bufA = bufB@W2 ; out = agg(bufA) + b2
    k_gemm64<64, false><<<gG, 256>>>(nullptr, W2, n);
    k_agg<false, true><<<gA, aggBlock>>>(b2, out, n);
}